// round 1
// baseline (speedup 1.0000x reference)
#include <cuda_runtime.h>

// Problem dims (fixed by the reference)
#define Bb   8
#define Cc   512
#define Ci   256
#define Hh   64
#define Ww   64
#define Nn   (Hh*Ww)          // 4096
#define Mm   ((Hh/2)*(Ww/2))  // 1024

// Scratch (device globals — no allocation allowed)
__device__ float g_full [Bb*Ci*Nn];          // reused: g full-res, then phi full-res
__device__ float g_xg   [Bb*Ci*Mm];
__device__ float g_xphi [Bb*Ci*Mm];
__device__ float g_xth  [Bb*Ci*Nn];
__device__ float g_f    [(size_t)Bb*Nn*Mm];  // 134 MB
__device__ float g_y    [Bb*Ci*Nn];

// ---------------------------------------------------------------------------
// Generic batched SGEMM: C[i,j] = sum_k A(i,k) * B(k,j)  (+ epilogue)
//   TA=0: A storage [I,K] row-major (a[i*lda+k]);  TA=1: A storage [K,I] (a[k*lda+i])
//   TB=0: B storage [K,J] (b[k*ldb+j]);            TB=1: B storage [J,K] (b[j*ldb+k])
//   EPI=0: plain store; EPI=1: +bias[i]; EPI=2: bias + inference-BN + residual
// Tile 128x128x8, 256 threads, 8x8 per thread. All dims divide tiles exactly.
// ---------------------------------------------------------------------------
template<int TA, int TB, int EPI>
__global__ __launch_bounds__(256)
void gemm128(const float* __restrict__ A,  int lda, long sA,
             const float* __restrict__ Bm, int ldb, long sB,
             float* __restrict__ Cm,       int ldc, long sC,
             int K,
             const float* __restrict__ bias,
             const float* __restrict__ gamma, const float* __restrict__ beta,
             const float* __restrict__ mean,  const float* __restrict__ var,
             const float* __restrict__ resid, long sR)
{
    const int bj = blockIdx.x * 128;
    const int bi = blockIdx.y * 128;
    const int b  = blockIdx.z;
    A  += (long)b * sA;
    Bm += (long)b * sB;
    Cm += (long)b * sC;

    __shared__ float As[8][128];
    __shared__ float Bs[8][128];

    const int t  = threadIdx.x;
    const int tx = t & 15;    // 0..15  -> j
    const int ty = t >> 4;    // 0..15  -> i

    float acc[8][8];
    #pragma unroll
    for (int i = 0; i < 8; i++)
        #pragma unroll
        for (int j = 0; j < 8; j++) acc[i][j] = 0.f;

    for (int k0 = 0; k0 < K; k0 += 8) {
        // ---- load A tile into As[k][i] ----
        if (TA == 0) {
            int i  = t >> 1;
            int k4 = (t & 1) * 4;
            float4 v = *(const float4*)(A + (long)(bi + i) * lda + (k0 + k4));
            As[k4+0][i] = v.x; As[k4+1][i] = v.y; As[k4+2][i] = v.z; As[k4+3][i] = v.w;
        } else {
            int k  = t >> 5;
            int i4 = (t & 31) * 4;
            *(float4*)&As[k][i4] = *(const float4*)(A + (long)(k0 + k) * lda + (bi + i4));
        }
        // ---- load B tile into Bs[k][j] ----
        if (TB == 0) {
            int k  = t >> 5;
            int j4 = (t & 31) * 4;
            *(float4*)&Bs[k][j4] = *(const float4*)(Bm + (long)(k0 + k) * ldb + (bj + j4));
        } else {
            int j  = t >> 1;
            int k4 = (t & 1) * 4;
            float4 v = *(const float4*)(Bm + (long)(bj + j) * ldb + (k0 + k4));
            Bs[k4+0][j] = v.x; Bs[k4+1][j] = v.y; Bs[k4+2][j] = v.z; Bs[k4+3][j] = v.w;
        }
        __syncthreads();

        #pragma unroll
        for (int k = 0; k < 8; k++) {
            float av[8], bv[8];
            #pragma unroll
            for (int r = 0; r < 8; r++) av[r] = As[k][ty*8 + r];
            #pragma unroll
            for (int r = 0; r < 8; r++) bv[r] = Bs[k][tx*8 + r];
            #pragma unroll
            for (int i = 0; i < 8; i++)
                #pragma unroll
                for (int j = 0; j < 8; j++)
                    acc[i][j] = fmaf(av[i], bv[j], acc[i][j]);
        }
        __syncthreads();
    }

    // ---- epilogue + store (vectorized float4) ----
    #pragma unroll
    for (int i = 0; i < 8; i++) {
        const int gi = bi + ty*8 + i;
        float scale = 1.f, shift = 0.f;
        if (EPI == 1) { shift = bias[gi]; }
        if (EPI == 2) {
            float s = gamma[gi] * rsqrtf(var[gi] + 1e-5f);
            scale = s;
            shift = (bias[gi] - mean[gi]) * s + beta[gi];
        }
        #pragma unroll
        for (int j4 = 0; j4 < 8; j4 += 4) {
            const long off = (long)gi * ldc + (bj + tx*8 + j4);
            float4 v;
            v.x = acc[i][j4+0]; v.y = acc[i][j4+1];
            v.z = acc[i][j4+2]; v.w = acc[i][j4+3];
            if (EPI == 2) {
                const float4 r = *(const float4*)(resid + (long)b * sR + off);
                v.x = v.x*scale + shift + r.x;
                v.y = v.y*scale + shift + r.y;
                v.z = v.z*scale + shift + r.z;
                v.w = v.w*scale + shift + r.w;
            } else if (EPI == 1) {
                v.x += shift; v.y += shift; v.z += shift; v.w += shift;
            }
            *(float4*)(Cm + off) = v;
        }
    }
}

// ---------------------------------------------------------------------------
// 2x2 max pool: [BC,64,64] -> [BC,32,32]
// ---------------------------------------------------------------------------
__global__ __launch_bounds__(256)
void maxpool2(const float* __restrict__ in, float* __restrict__ out, int total)
{
    int o = blockIdx.x * blockDim.x + threadIdx.x;
    if (o >= total) return;
    int mw = o & 31;
    int mh = (o >> 5) & 31;
    int bc = o >> 10;
    const float* p = in + ((long)bc * 64 + mh * 2) * 64 + mw * 2;
    out[o] = fmaxf(fmaxf(p[0], p[1]), fmaxf(p[64], p[65]));
}

// ---------------------------------------------------------------------------
// Row softmax over M=1024; one block (256 threads) per row, float4 per thread
// ---------------------------------------------------------------------------
__global__ __launch_bounds__(256)
void softmax1024(float* __restrict__ f)
{
    const long row = blockIdx.x;
    float4* p = (float4*)(f + row * (long)Mm);
    const int t = threadIdx.x;

    float4 v = p[t];
    float lm = fmaxf(fmaxf(v.x, v.y), fmaxf(v.z, v.w));
    #pragma unroll
    for (int o = 16; o; o >>= 1) lm = fmaxf(lm, __shfl_xor_sync(0xffffffffu, lm, o));

    __shared__ float sm[8];
    if ((t & 31) == 0) sm[t >> 5] = lm;
    __syncthreads();
    float m = sm[0];
    #pragma unroll
    for (int i = 1; i < 8; i++) m = fmaxf(m, sm[i]);
    __syncthreads();

    v.x = __expf(v.x - m);
    v.y = __expf(v.y - m);
    v.z = __expf(v.z - m);
    v.w = __expf(v.w - m);
    float ls = v.x + v.y + v.z + v.w;
    #pragma unroll
    for (int o = 16; o; o >>= 1) ls += __shfl_xor_sync(0xffffffffu, ls, o);
    if ((t & 31) == 0) sm[t >> 5] = ls;
    __syncthreads();
    float s = sm[0];
    #pragma unroll
    for (int i = 1; i < 8; i++) s += sm[i];

    const float inv = 1.f / s;
    v.x *= inv; v.y *= inv; v.z *= inv; v.w *= inv;
    p[t] = v;
}

// ---------------------------------------------------------------------------
extern "C" void kernel_launch(void* const* d_in, const int* in_sizes, int n_in,
                              void* d_out, int out_size)
{
    const float* x     = (const float*)d_in[0];
    const float* gw    = (const float*)d_in[1];
    const float* gb    = (const float*)d_in[2];
    const float* thw   = (const float*)d_in[3];
    const float* thb   = (const float*)d_in[4];
    const float* phw   = (const float*)d_in[5];
    const float* phb   = (const float*)d_in[6];
    const float* ww    = (const float*)d_in[7];
    const float* wb    = (const float*)d_in[8];
    const float* gamma = (const float*)d_in[9];
    const float* beta  = (const float*)d_in[10];
    const float* mean  = (const float*)d_in[11];
    const float* var   = (const float*)d_in[12];
    float* out = (float*)d_out;

    float *full, *xg, *xphi, *xth, *f, *y;
    cudaGetSymbolAddress((void**)&full, g_full);
    cudaGetSymbolAddress((void**)&xg,   g_xg);
    cudaGetSymbolAddress((void**)&xphi, g_xphi);
    cudaGetSymbolAddress((void**)&xth,  g_xth);
    cudaGetSymbolAddress((void**)&f,    g_f);
    cudaGetSymbolAddress((void**)&y,    g_y);

    const dim3 thr(256);

    // 1) g projection: [Ci,Cc] x [Cc,Nn] per batch -> full
    {
        dim3 grid(Nn/128, Ci/128, Bb);
        gemm128<0,0,1><<<grid, thr>>>(gw, Cc, 0, x, Nn, (long)Cc*Nn,
                                      full, Nn, (long)Ci*Nn, Cc,
                                      gb, nullptr,nullptr,nullptr,nullptr, nullptr, 0);
    }
    maxpool2<<<(Bb*Ci*Mm + 255)/256, thr>>>(full, xg, Bb*Ci*Mm);

    // 2) phi projection -> full (reused), then pool
    {
        dim3 grid(Nn/128, Ci/128, Bb);
        gemm128<0,0,1><<<grid, thr>>>(phw, Cc, 0, x, Nn, (long)Cc*Nn,
                                      full, Nn, (long)Ci*Nn, Cc,
                                      phb, nullptr,nullptr,nullptr,nullptr, nullptr, 0);
    }
    maxpool2<<<(Bb*Ci*Mm + 255)/256, thr>>>(full, xphi, Bb*Ci*Mm);

    // 3) theta projection -> xth  [Ci, Nn] per batch
    {
        dim3 grid(Nn/128, Ci/128, Bb);
        gemm128<0,0,1><<<grid, thr>>>(thw, Cc, 0, x, Nn, (long)Cc*Nn,
                                      xth, Nn, (long)Ci*Nn, Cc,
                                      thb, nullptr,nullptr,nullptr,nullptr, nullptr, 0);
    }

    // 4) affinity: f[n,m] = sum_c xth[c,n] * xphi[c,m]   (TA=1, TB=0), K=Ci
    {
        dim3 grid(Mm/128, Nn/128, Bb);
        gemm128<1,0,0><<<grid, thr>>>(xth, Nn, (long)Ci*Nn, xphi, Mm, (long)Ci*Mm,
                                      f, Mm, (long)Nn*Mm, Ci,
                                      nullptr, nullptr,nullptr,nullptr,nullptr, nullptr, 0);
    }

    // 5) softmax over m
    softmax1024<<<Bb*Nn, thr>>>(f);

    // 6) apply: y[c,n] = sum_m xg[c,m] * f[n,m]   (TA=0, TB=1), K=Mm
    {
        dim3 grid(Nn/128, Ci/128, Bb);
        gemm128<0,1,0><<<grid, thr>>>(xg, Mm, (long)Ci*Mm, f, Mm, (long)Nn*Mm,
                                      y, Nn, (long)Ci*Nn, Mm,
                                      nullptr, nullptr,nullptr,nullptr,nullptr, nullptr, 0);
    }

    // 7) output conv + BN + residual: out[o,n] = BN(sum_c ww[o,c]*y[c,n] + wb) + x
    {
        dim3 grid(Nn/128, Cc/128, Bb);
        gemm128<0,0,2><<<grid, thr>>>(ww, Ci, 0, y, Nn, (long)Ci*Nn,
                                      out, Nn, (long)Cc*Nn, Ci,
                                      wb, gamma, beta, mean, var, x, (long)Cc*Nn);
    }
}

// round 5
// speedup vs baseline: 1.8803x; 1.8803x over previous
#include <cuda_runtime.h>
#include <cuda_bf16.h>
#include <cstdint>

#define Bb 8
#define Cc 512
#define Ci 256
#define Nn 4096
#define Mm 1024

using bf16 = __nv_bfloat16;

// ---------------- device scratch (static; no allocation allowed) ----------------
__device__ __align__(128) bf16 d_xT_h[(size_t)Bb*Nn*Cc], d_xT_l[(size_t)Bb*Nn*Cc];   // x^T split [b][n][c]
__device__ __align__(128) bf16 d_wg_h [Ci*Cc], d_wg_l [Ci*Cc];
__device__ __align__(128) bf16 d_wth_h[Ci*Cc], d_wth_l[Ci*Cc];
__device__ __align__(128) bf16 d_wph_h[Ci*Cc], d_wph_l[Ci*Cc];
__device__ __align__(128) bf16 d_ww_h [Cc*Ci], d_ww_l [Cc*Ci];
__device__ __align__(128) bf16 d_xth_h [(size_t)Bb*Nn*Ci], d_xth_l [(size_t)Bb*Nn*Ci]; // theta [b][n][ci]
__device__ __align__(128) bf16 d_phif_h[(size_t)Bb*Nn*Ci], d_phif_l[(size_t)Bb*Nn*Ci]; // phi full [b][n][ci]
__device__ __align__(128) bf16 d_xphi_h[(size_t)Bb*Mm*Ci], d_xphi_l[(size_t)Bb*Mm*Ci]; // phi pooled [b][m][ci]
__device__ __align__(128) bf16 d_gf_h  [(size_t)Bb*Ci*Nn], d_gf_l  [(size_t)Bb*Ci*Nn]; // g full [b][ci][n]
__device__ __align__(128) bf16 d_xg_h  [(size_t)Bb*Ci*Mm], d_xg_l  [(size_t)Bb*Ci*Mm]; // g pooled [b][ci][m]
__device__ __align__(128) float d_f    [(size_t)Bb*Nn*Mm];                              // logits (fp32)
__device__ __align__(128) bf16 d_f_h   [(size_t)Bb*Nn*Mm], d_f_l[(size_t)Bb*Nn*Mm];    // softmax split
__device__ __align__(128) bf16 d_y_h   [(size_t)Bb*Nn*Ci], d_y_l[(size_t)Bb*Nn*Ci];    // y [b][n][ci]

// ---------------- PTX helpers (baseline sm_80+ ISA only) ----------------
__device__ __forceinline__ uint32_t smem_u32(const void* p) {
    uint32_t a;
    asm("{ .reg .u64 t; cvta.to.shared.u64 t, %1; cvt.u32.u64 %0, t; }" : "=r"(a) : "l"(p));
    return a;
}
__device__ __forceinline__ void cp16(uint32_t dst, const void* src) {
    asm volatile("cp.async.cg.shared.global [%0], [%1], 16;" :: "r"(dst), "l"(src));
}
#define CP_COMMIT() asm volatile("cp.async.commit_group;" ::: "memory")
#define CP_WAIT(n)  asm volatile("cp.async.wait_group %0;" :: "n"(n) : "memory")

__device__ __forceinline__ void mma16816(float* c, const uint32_t* a, const uint32_t* b) {
    asm volatile("mma.sync.aligned.m16n8k16.row.col.f32.bf16.bf16.f32 "
                 "{%0,%1,%2,%3}, {%4,%5,%6,%7}, {%8,%9}, {%0,%1,%2,%3};"
                 : "+f"(c[0]), "+f"(c[1]), "+f"(c[2]), "+f"(c[3])
                 : "r"(a[0]), "r"(a[1]), "r"(a[2]), "r"(a[3]), "r"(b[0]), "r"(b[1]));
}

// smem tile: 128 rows x 32 bf16; row stride 20 words (80B) for 16B-aligned
// cp.async chunks and conflict-free LDS fragment reads.
static constexpr int ROW_W       = 20;               // 32-bit words per row
static constexpr int TILE_WORDS  = 128 * ROW_W;      // 2560 words = 10240 B per tile
static constexpr int STAGE_WORDS = 2 * TILE_WORDS;   // A + B = 5120 words = 20480 B
__shared__ uint32_t __align__(16) s_pipe[2 * STAGE_WORDS];   // 40 KB static

// issue cp.async loads for one K-stage (32 k-elems) of A(128 rows) + B(128 rows)
// NOTE: A/B pointers must already be offset by the CTA tile (bi*lda / bj*ldb).
__device__ __forceinline__ void stage_loads(
    int it, int niter, int nsub, int tid, uint32_t smb,
    const bf16* Ah, const bf16* Al, int lda,
    const bf16* Bh, const bf16* Bl, int ldb)
{
    if (it < niter) {
        const int phase = it / nsub;
        const int k0    = (it - phase * nsub) << 5;
        const bf16* Asrc = (phase == 2) ? Al : Ah;
        const bf16* Bsrc = (phase == 1) ? Bl : Bh;
        const uint32_t sb = smb + (uint32_t)(it & 1) * (STAGE_WORDS * 4);
        const int c = tid & 3;                 // 16B chunk within row
        #pragma unroll
        for (int h = 0; h < 2; h++) {
            const int r = (tid >> 2) + h * 64;
            const uint32_t ro = (uint32_t)(r * ROW_W * 4 + c * 16);
            cp16(sb + ro,                  Asrc + (size_t)r * lda + k0 + c * 8);
            cp16(sb + TILE_WORDS * 4 + ro, Bsrc + (size_t)r * ldb + k0 + c * 8);
        }
    }
    CP_COMMIT();
}

// ---------------------------------------------------------------------------
// bf16 split GEMM via mma.sync: D[i,j] = sum_k A(i,k)*B(j,k) (NT form),
// tile 128x128, Ktile=32, 3-phase split accumulation (hh + h*l + l*h) in fp32.
// Fragments gathered with plain LDS.32 (no ldmatrix).
// EPI: 0 = fp32 store, 1 = (+bias) split-bf16 store, 2 = BN+bias+residual fp32
// ---------------------------------------------------------------------------
template<int EPI>
__global__ void __launch_bounds__(256, 2)
mma_gemm(const bf16* __restrict__ Ah, const bf16* __restrict__ Al, int lda, long sA,
         const bf16* __restrict__ Bh, const bf16* __restrict__ Bl, int ldb, long sB,
         int K,
         float* __restrict__ Cf, bf16* __restrict__ Ch, bf16* __restrict__ Cl,
         int ldc, long sC,
         const float* __restrict__ bias, int bias_col,
         const float* __restrict__ gamma, const float* __restrict__ beta,
         const float* __restrict__ mean,  const float* __restrict__ var,
         const float* __restrict__ resid)
{
    const int tid  = threadIdx.x;
    const int wid  = tid >> 5;
    const int lane = tid & 31;
    const int gid  = lane >> 2;      // 0..7
    const int tidg = lane & 3;       // 0..3
    const int bi = blockIdx.y * 128;
    const int bj = blockIdx.x * 128;
    const int b  = blockIdx.z;
    // batch offset AND tile offset (the R3/R4 bug: bi/bj were missing)
    Ah += (size_t)b * sA + (size_t)bi * lda;
    Al += (size_t)b * sA + (size_t)bi * lda;
    Bh += (size_t)b * sB + (size_t)bj * ldb;
    Bl += (size_t)b * sB + (size_t)bj * ldb;

    const uint32_t smb = smem_u32(s_pipe);
    const int nsub  = K >> 5;
    const int niter = 3 * nsub;

    float acc[4][4][4];
    #pragma unroll
    for (int mi = 0; mi < 4; mi++)
        #pragma unroll
        for (int ni = 0; ni < 4; ni++)
            #pragma unroll
            for (int e = 0; e < 4; e++) acc[mi][ni][e] = 0.f;

    const int wm = wid & 1;          // 0..1 -> M half (64 rows)
    const int wn = wid >> 1;         // 0..3 -> N quarter (32 rows)

    // per-thread fragment word bases (word units)
    const int aBase = (wm * 64 + gid) * ROW_W + tidg;   // + mi*16*ROW_W + s*8 (+4 for k-hi, +8*ROW_W for row+8)
    const int bBase = (wn * 32 + gid) * ROW_W + tidg;   // + ni*8*ROW_W  + s*8 (+4 for k-hi)

    // prologue: stage 0
    stage_loads(0, niter, nsub, tid, smb, Ah, Al, lda, Bh, Bl, ldb);

    for (int it = 0; it < niter; ++it) {
        stage_loads(it + 1, niter, nsub, tid, smb, Ah, Al, lda, Bh, Bl, ldb);
        CP_WAIT(1);
        __syncthreads();

        const uint32_t* As = s_pipe + (it & 1) * STAGE_WORDS;
        const uint32_t* Bs = As + TILE_WORDS;

        #pragma unroll
        for (int s = 0; s < 2; s++) {            // two k16 steps per 32-K stage
            uint32_t a[4][4];
            uint32_t bfr[4][2];
            #pragma unroll
            for (int mi = 0; mi < 4; mi++) {
                const int p = aBase + mi * (16 * ROW_W) + s * 8;
                a[mi][0] = As[p];                    // (row gid,    k-lo)
                a[mi][1] = As[p + 8 * ROW_W];        // (row gid+8,  k-lo)
                a[mi][2] = As[p + 4];                // (row gid,    k-hi)
                a[mi][3] = As[p + 8 * ROW_W + 4];    // (row gid+8,  k-hi)
            }
            #pragma unroll
            for (int ni = 0; ni < 4; ni++) {
                const int p = bBase + ni * (8 * ROW_W) + s * 8;
                bfr[ni][0] = Bs[p];                  // (n gid, k-lo)
                bfr[ni][1] = Bs[p + 4];              // (n gid, k-hi)
            }
            #pragma unroll
            for (int mi = 0; mi < 4; mi++)
                #pragma unroll
                for (int ni = 0; ni < 4; ni++)
                    mma16816(acc[mi][ni], a[mi], bfr[ni]);
        }
        __syncthreads();
    }
    CP_WAIT(0);

    // ---- epilogue: register fragments -> gmem ----
    const int tr = gid;
    const int tc = tidg * 2;
    #pragma unroll
    for (int mi = 0; mi < 4; mi++) {
        #pragma unroll
        for (int h = 0; h < 2; h++) {
            const int gi = bi + wm * 64 + mi * 16 + tr + 8 * h;
            float scale = 1.f, shift = 0.f;
            if (EPI == 1 && !bias_col && bias) shift = bias[gi];
            if (EPI == 2) {
                const float sc = gamma[gi] * rsqrtf(var[gi] + 1e-5f);
                scale = sc;
                shift = (bias[gi] - mean[gi]) * sc + beta[gi];
            }
            #pragma unroll
            for (int ni = 0; ni < 4; ni++) {
                const int gj = bj + wn * 32 + ni * 8 + tc;
                const size_t off = (size_t)b * sC + (size_t)gi * ldc + gj;
                float v0 = acc[mi][ni][2*h];
                float v1 = acc[mi][ni][2*h + 1];
                if (EPI == 0) {
                    *(float2*)(Cf + off) = make_float2(v0, v1);
                } else if (EPI == 1) {
                    if (bias_col && bias) { v0 += bias[gj]; v1 += bias[gj + 1]; }
                    else                  { v0 += shift;    v1 += shift; }
                    const bf16 h0 = __float2bfloat16(v0);
                    const bf16 h1 = __float2bfloat16(v1);
                    __nv_bfloat162 hv; hv.x = h0; hv.y = h1;
                    __nv_bfloat162 lv;
                    lv.x = __float2bfloat16(v0 - __bfloat162float(h0));
                    lv.y = __float2bfloat16(v1 - __bfloat162float(h1));
                    *(__nv_bfloat162*)(Ch + off) = hv;
                    *(__nv_bfloat162*)(Cl + off) = lv;
                } else {
                    const float2 r2 = *(const float2*)(resid + off);
                    *(float2*)(Cf + off) = make_float2(v0 * scale + shift + r2.x,
                                                       v1 * scale + shift + r2.y);
                }
            }
        }
    }
}

// ---------------------------------------------------------------------------
// helpers: splits, transpose, pools, softmax
// ---------------------------------------------------------------------------
__global__ void __launch_bounds__(256) split_w(const float* __restrict__ w,
                                               bf16* __restrict__ h, bf16* __restrict__ l, int n)
{
    int i = blockIdx.x * 256 + threadIdx.x;
    if (i < n) {
        float v = w[i];
        bf16 hh = __float2bfloat16(v);
        h[i] = hh;
        l[i] = __float2bfloat16(v - __bfloat162float(hh));
    }
}

__global__ void tsplit_x(const float* __restrict__ x, bf16* __restrict__ th, bf16* __restrict__ tl)
{
    __shared__ float t[32][33];
    int b = blockIdx.z, n0 = blockIdx.x * 32, c0 = blockIdx.y * 32;
    const float* xp = x + ((size_t)b * Cc + c0) * Nn + n0;
    for (int i = threadIdx.y; i < 32; i += 8)
        t[i][threadIdx.x] = xp[(size_t)i * Nn + threadIdx.x];   // t[c][n]
    __syncthreads();
    size_t ob = ((size_t)b * Nn + n0) * Cc + c0;
    for (int i = threadIdx.y; i < 32; i += 8) {
        float v = t[threadIdx.x][i];
        bf16 hh = __float2bfloat16(v);
        th[ob + (size_t)i * Cc + threadIdx.x] = hh;
        tl[ob + (size_t)i * Cc + threadIdx.x] = __float2bfloat16(v - __bfloat162float(hh));
    }
}

__device__ __forceinline__ float rec2(const bf16* h, const bf16* l, size_t i) {
    return __bfloat162float(h[i]) + __bfloat162float(l[i]);
}
__device__ __forceinline__ void wsplit(bf16* h, bf16* l, size_t i, float v) {
    bf16 hh = __float2bfloat16(v);
    h[i] = hh;
    l[i] = __float2bfloat16(v - __bfloat162float(hh));
}

// phi full [b][n][ci] -> pooled [b][m][ci]
__global__ void __launch_bounds__(256) pool_phi(const bf16* __restrict__ ih, const bf16* __restrict__ il,
                                                bf16* __restrict__ oh, bf16* __restrict__ ol)
{
    int idx = blockIdx.x * 256 + threadIdx.x;           // Bb*Mm*Ci
    int ci = idx & 255;
    int m  = (idx >> 8) & 1023;
    int b  = idx >> 18;
    int n00 = ((m >> 5) * 2) * 64 + (m & 31) * 2;
    size_t p0 = (size_t)b * Nn * Ci + (size_t)n00 * Ci + ci;
    float v = fmaxf(fmaxf(rec2(ih, il, p0), rec2(ih, il, p0 + Ci)),
                    fmaxf(rec2(ih, il, p0 + 64 * Ci), rec2(ih, il, p0 + 65 * Ci)));
    wsplit(oh, ol, ((size_t)b * Mm + m) * Ci + ci, v);
}

// g full [b][ci][n] -> pooled [b][ci][m]
__global__ void __launch_bounds__(256) pool_g(const bf16* __restrict__ ih, const bf16* __restrict__ il,
                                              bf16* __restrict__ oh, bf16* __restrict__ ol)
{
    int idx = blockIdx.x * 256 + threadIdx.x;           // Bb*Ci*Mm
    int m  = idx & 1023;
    int ci = (idx >> 10) & 255;
    int b  = idx >> 18;
    int n00 = ((m >> 5) * 2) * 64 + (m & 31) * 2;
    size_t ib = ((size_t)b * Ci + ci) * Nn + n00;
    float v = fmaxf(fmaxf(rec2(ih, il, ib), rec2(ih, il, ib + 1)),
                    fmaxf(rec2(ih, il, ib + 64), rec2(ih, il, ib + 65)));
    wsplit(oh, ol, ((size_t)b * Ci + ci) * Mm + m, v);
}

__global__ void __launch_bounds__(256) softmax_split(const float* __restrict__ f,
                                                     bf16* __restrict__ fh, bf16* __restrict__ fl)
{
    const size_t row = blockIdx.x;
    const float4* p = (const float4*)(f + row * Mm);
    const int t = threadIdx.x;
    float4 v = p[t];
    float lm = fmaxf(fmaxf(v.x, v.y), fmaxf(v.z, v.w));
    #pragma unroll
    for (int o = 16; o; o >>= 1) lm = fmaxf(lm, __shfl_xor_sync(0xffffffffu, lm, o));
    __shared__ float red[8];
    if ((t & 31) == 0) red[t >> 5] = lm;
    __syncthreads();
    float mx = red[0];
    #pragma unroll
    for (int i = 1; i < 8; i++) mx = fmaxf(mx, red[i]);
    __syncthreads();
    v.x = __expf(v.x - mx); v.y = __expf(v.y - mx);
    v.z = __expf(v.z - mx); v.w = __expf(v.w - mx);
    float ls = v.x + v.y + v.z + v.w;
    #pragma unroll
    for (int o = 16; o; o >>= 1) ls += __shfl_xor_sync(0xffffffffu, ls, o);
    if ((t & 31) == 0) red[t >> 5] = ls;
    __syncthreads();
    float s = red[0];
    #pragma unroll
    for (int i = 1; i < 8; i++) s += red[i];
    const float inv = 1.f / s;
    size_t off = row * Mm + t * 4;
    #pragma unroll
    for (int e = 0; e < 4; e++) {
        float val = ((&v.x)[e]) * inv;
        bf16 hh = __float2bfloat16(val);
        fh[off + e] = hh;
        fl[off + e] = __float2bfloat16(val - __bfloat162float(hh));
    }
}

// ---------------------------------------------------------------------------
extern "C" void kernel_launch(void* const* d_in, const int* in_sizes, int n_in,
                              void* d_out, int out_size)
{
    const float* x     = (const float*)d_in[0];
    const float* gw    = (const float*)d_in[1];
    const float* gb    = (const float*)d_in[2];
    const float* thw   = (const float*)d_in[3];
    const float* thb   = (const float*)d_in[4];
    const float* phw   = (const float*)d_in[5];
    const float* phb   = (const float*)d_in[6];
    const float* ww    = (const float*)d_in[7];
    const float* wb    = (const float*)d_in[8];
    const float* gamma = (const float*)d_in[9];
    const float* beta  = (const float*)d_in[10];
    const float* mean  = (const float*)d_in[11];
    const float* var   = (const float*)d_in[12];
    float* out = (float*)d_out;

#define GA(v, s) void* v; cudaGetSymbolAddress(&v, s)
    GA(xT_h, d_xT_h);   GA(xT_l, d_xT_l);
    GA(wg_h, d_wg_h);   GA(wg_l, d_wg_l);
    GA(wth_h, d_wth_h); GA(wth_l, d_wth_l);
    GA(wph_h, d_wph_h); GA(wph_l, d_wph_l);
    GA(ww_h, d_ww_h);   GA(ww_l, d_ww_l);
    GA(xth_h, d_xth_h); GA(xth_l, d_xth_l);
    GA(phif_h, d_phif_h); GA(phif_l, d_phif_l);
    GA(xphi_h, d_xphi_h); GA(xphi_l, d_xphi_l);
    GA(gf_h, d_gf_h);   GA(gf_l, d_gf_l);
    GA(xg_h, d_xg_h);   GA(xg_l, d_xg_l);
    GA(fbuf, d_f);
    GA(f_h, d_f_h);     GA(f_l, d_f_l);
    GA(y_h, d_y_h);     GA(y_l, d_y_l);
#undef GA

    const dim3 thr(256);

    // weight splits
    split_w<<<(Ci*Cc + 255) / 256, thr>>>(gw,  (bf16*)wg_h,  (bf16*)wg_l,  Ci*Cc);
    split_w<<<(Ci*Cc + 255) / 256, thr>>>(thw, (bf16*)wth_h, (bf16*)wth_l, Ci*Cc);
    split_w<<<(Ci*Cc + 255) / 256, thr>>>(phw, (bf16*)wph_h, (bf16*)wph_l, Ci*Cc);
    split_w<<<(Cc*Ci + 255) / 256, thr>>>(ww,  (bf16*)ww_h,  (bf16*)ww_l,  Cc*Ci);

    // x transpose + split -> xT [b][n][c]
    tsplit_x<<<dim3(Nn/32, Cc/32, Bb), dim3(32, 8)>>>(x, (bf16*)xT_h, (bf16*)xT_l);

    // theta: D[n,ci] = sum_c xT[n,c]*Wth[ci,c]  (bias over cols=ci)
    mma_gemm<1><<<dim3(Ci/128, Nn/128, Bb), thr>>>(
        (bf16*)xT_h, (bf16*)xT_l, Cc, (long)Nn*Cc,
        (bf16*)wth_h, (bf16*)wth_l, Cc, 0, Cc,
        nullptr, (bf16*)xth_h, (bf16*)xth_l, Ci, (long)Nn*Ci,
        thb, 1, nullptr, nullptr, nullptr, nullptr, nullptr);

    // phi full: D[n,ci]
    mma_gemm<1><<<dim3(Ci/128, Nn/128, Bb), thr>>>(
        (bf16*)xT_h, (bf16*)xT_l, Cc, (long)Nn*Cc,
        (bf16*)wph_h, (bf16*)wph_l, Cc, 0, Cc,
        nullptr, (bf16*)phif_h, (bf16*)phif_l, Ci, (long)Nn*Ci,
        phb, 1, nullptr, nullptr, nullptr, nullptr, nullptr);
    pool_phi<<<(Bb*Mm*Ci) / 256, thr>>>((bf16*)phif_h, (bf16*)phif_l, (bf16*)xphi_h, (bf16*)xphi_l);

    // g full: D[ci,n]  (bias over rows=ci)
    mma_gemm<1><<<dim3(Nn/128, Ci/128, Bb), thr>>>(
        (bf16*)wg_h, (bf16*)wg_l, Cc, 0,
        (bf16*)xT_h, (bf16*)xT_l, Cc, (long)Nn*Cc, Cc,
        nullptr, (bf16*)gf_h, (bf16*)gf_l, Nn, (long)Ci*Nn,
        gb, 0, nullptr, nullptr, nullptr, nullptr, nullptr);
    pool_g<<<(Bb*Ci*Mm) / 256, thr>>>((bf16*)gf_h, (bf16*)gf_l, (bf16*)xg_h, (bf16*)xg_l);

    // affinity: f[n,m] = sum_ci xth[n,ci]*xphi[m,ci]  -> fp32
    mma_gemm<0><<<dim3(Mm/128, Nn/128, Bb), thr>>>(
        (bf16*)xth_h, (bf16*)xth_l, Ci, (long)Nn*Ci,
        (bf16*)xphi_h, (bf16*)xphi_l, Ci, (long)Mm*Ci, Ci,
        (float*)fbuf, nullptr, nullptr, Mm, (long)Nn*Mm,
        nullptr, 0, nullptr, nullptr, nullptr, nullptr, nullptr);

    softmax_split<<<Bb*Nn, thr>>>((const float*)fbuf, (bf16*)f_h, (bf16*)f_l);

    // apply: y[n,ci] = sum_m f[n,m]*xg[ci,m]
    mma_gemm<1><<<dim3(Ci/128, Nn/128, Bb), thr>>>(
        (bf16*)f_h, (bf16*)f_l, Mm, (long)Nn*Mm,
        (bf16*)xg_h, (bf16*)xg_l, Mm, (long)Ci*Mm, Mm,
        nullptr, (bf16*)y_h, (bf16*)y_l, Ci, (long)Nn*Ci,
        nullptr, 0, nullptr, nullptr, nullptr, nullptr, nullptr);

    // output conv + BN + residual: out[co,n] = BN(sum_ci ww[co,ci]*y[n,ci] + wb) + x
    mma_gemm<2><<<dim3(Nn/128, Cc/128, Bb), thr>>>(
        (bf16*)ww_h, (bf16*)ww_l, Ci, 0,
        (bf16*)y_h, (bf16*)y_l, Ci, (long)Nn*Ci, Ci,
        out, nullptr, nullptr, Nn, (long)Cc*Nn,
        wb, 0, gamma, beta, mean, var, x);
}